// round 2
// baseline (speedup 1.0000x reference)
#include <cuda_runtime.h>

// Problem constants
#define B_    32
#define N_    1024
#define DIN_  256
#define DOUT_ 256

// Scratch (device globals; allocation inside kernel_launch is forbidden)
__device__ float g_q[B_ * N_ * DOUT_];                 // 32 MB
__device__ float g_k[B_ * N_ * DOUT_];                 // 32 MB
__device__ float g_v[B_ * N_ * DOUT_];                 // 32 MB
__device__ float g_logits[(long long)B_ * N_ * N_];    // 128 MB (logits -> attn in place)

// ---------------------------------------------------------------------------
// Generic register-blocked fp32 GEMM.
//   C[m,n] = sum_k A[m,k] * B'[...] (+ bias[n])
// BLAYOUT = 0 ("NT"): B is (Nn x K) row-major, B[n,k]  (weights / k-matrix)
// BLAYOUT = 1 ("NN"): B is (K x Nn) row-major, B[k,n]  (v-matrix)
// Tile: BM=128, BN=128, BK=16; 256 threads, 8x8 per thread.
// All dims are multiples of tile sizes for this problem -> no bounds checks.
// blockIdx.z selects batch via strides sA/sB/sC.
// ---------------------------------------------------------------------------
template <int BLAYOUT, int HASBIAS>
__global__ __launch_bounds__(256, 2)
void gemm_kernel(const float* __restrict__ A, const float* __restrict__ Bm,
                 const float* __restrict__ bias, float* __restrict__ C,
                 int M, int Nn, int K,
                 int ldA, int ldB, int ldC,
                 long long sA, long long sB, long long sC)
{
    const int bz = blockIdx.z;
    A  += (long long)bz * sA;
    Bm += (long long)bz * sB;
    C  += (long long)bz * sC;

    __shared__ float As[16][128];
    __shared__ float Bs[16][128];

    const int tid  = threadIdx.x;
    const int row0 = blockIdx.y * 128;
    const int col0 = blockIdx.x * 128;

    // A-tile (and NT B-tile) load mapping: float4 along k, stored transposed
    const int aRow = tid / 4;          // 0..63
    const int aCol = (tid % 4) * 4;    // 0,4,8,12
    // NN B-tile load mapping: float4 along n
    const int bRow = tid / 32;         // 0..7
    const int bCol = (tid % 32) * 4;   // 0..124

    const int ty = tid / 16;           // 0..15
    const int tx = tid % 16;           // 0..15

    float acc[8][8];
#pragma unroll
    for (int i = 0; i < 8; i++)
#pragma unroll
        for (int j = 0; j < 8; j++) acc[i][j] = 0.0f;

    for (int k0 = 0; k0 < K; k0 += 16) {
        // ---- load A tile (transposed into As[k][m]) ----
#pragma unroll
        for (int off = 0; off < 128; off += 64) {
            float4 t = *reinterpret_cast<const float4*>(
                &A[(long long)(row0 + aRow + off) * ldA + k0 + aCol]);
            As[aCol + 0][aRow + off] = t.x;
            As[aCol + 1][aRow + off] = t.y;
            As[aCol + 2][aRow + off] = t.z;
            As[aCol + 3][aRow + off] = t.w;
        }
        // ---- load B tile ----
        if (BLAYOUT == 0) {
#pragma unroll
            for (int off = 0; off < 128; off += 64) {
                float4 t = *reinterpret_cast<const float4*>(
                    &Bm[(long long)(col0 + aRow + off) * ldB + k0 + aCol]);
                Bs[aCol + 0][aRow + off] = t.x;
                Bs[aCol + 1][aRow + off] = t.y;
                Bs[aCol + 2][aRow + off] = t.z;
                Bs[aCol + 3][aRow + off] = t.w;
            }
        } else {
#pragma unroll
            for (int off = 0; off < 16; off += 8) {
                float4 t = *reinterpret_cast<const float4*>(
                    &Bm[(long long)(k0 + bRow + off) * ldB + col0 + bCol]);
                *reinterpret_cast<float4*>(&Bs[bRow + off][bCol]) = t;
            }
        }
        __syncthreads();

        // ---- compute ----
#pragma unroll
        for (int kk = 0; kk < 16; kk++) {
            float ra[8], rb[8];
#pragma unroll
            for (int i = 0; i < 8; i++) ra[i] = As[kk][ty * 8 + i];
#pragma unroll
            for (int j = 0; j < 8; j++) rb[j] = Bs[kk][tx * 8 + j];
#pragma unroll
            for (int i = 0; i < 8; i++)
#pragma unroll
                for (int j = 0; j < 8; j++)
                    acc[i][j] = fmaf(ra[i], rb[j], acc[i][j]);
        }
        __syncthreads();
    }

    // ---- epilogue ----
#pragma unroll
    for (int i = 0; i < 8; i++) {
        const int r = row0 + ty * 8 + i;
#pragma unroll
        for (int j0 = 0; j0 < 8; j0 += 4) {
            const int c = col0 + tx * 8 + j0;
            float4 o;
            o.x = acc[i][j0 + 0];
            o.y = acc[i][j0 + 1];
            o.z = acc[i][j0 + 2];
            o.w = acc[i][j0 + 3];
            if (HASBIAS) {
                o.x += bias[c + 0];
                o.y += bias[c + 1];
                o.z += bias[c + 2];
                o.w += bias[c + 3];
            }
            *reinterpret_cast<float4*>(&C[(long long)r * ldC + c]) = o;
        }
    }
}

// ---------------------------------------------------------------------------
// Softmax over the BATCH axis (axis=0), in place on g_logits.
// attn[b,n,m] = exp(l[b,n,m] - max_b) / sum_b exp(...)
// One thread per (n,m); 32 values live in registers.
// exp computed with FMA-pipe polynomial (avoids the MUFU throughput wall:
// 32M MUFU exps would cost ~230 us on their own).
// ---------------------------------------------------------------------------
__device__ __forceinline__ float fexp_poly(float x)
{
    // x <= 0 expected; clamp for exponent-bit safety
    float t = fmaxf(x, -100.0f) * 1.4426950408889634f;  // x * log2(e)
    float r = rintf(t);
    float f = t - r;                                    // f in [-0.5, 0.5]
    // exp(f * ln2) Taylor, degree 5 (max rel err ~2.4e-6)
    float p = 0.0013333558f;
    p = fmaf(p, f, 0.0096181291f);
    p = fmaf(p, f, 0.0555041087f);
    p = fmaf(p, f, 0.2402265070f);
    p = fmaf(p, f, 0.6931471806f);
    p = fmaf(p, f, 1.0f);
    int e = (int)r;                                     // e in [-145, 0] after clamp
    float sc = __int_as_float((e + 127) << 23);         // 2^e (normal range)
    return p * sc;
}

__global__ __launch_bounds__(256)
void softmax_b_kernel(float* __restrict__ lg)
{
    const int idx = blockIdx.x * blockDim.x + threadIdx.x;  // (n*N + m)
    const int stride = N_ * N_;

    float vals[B_];
    float mx = -1e30f;
#pragma unroll
    for (int b = 0; b < B_; b++) {
        vals[b] = lg[b * stride + idx];
        mx = fmaxf(mx, vals[b]);
    }
    float s = 0.0f;
#pragma unroll
    for (int b = 0; b < B_; b++) {
        float ev = fexp_poly(vals[b] - mx);
        vals[b] = ev;
        s += ev;
    }
    const float inv = 1.0f / s;
#pragma unroll
    for (int b = 0; b < B_; b++)
        lg[b * stride + idx] = vals[b] * inv;
}

// ---------------------------------------------------------------------------
extern "C" void kernel_launch(void* const* d_in, const int* in_sizes, int n_in,
                              void* d_out, int out_size)
{
    const float* x  = (const float*)d_in[0];
    const float* Wq = (const float*)d_in[1];
    const float* bq = (const float*)d_in[2];
    const float* Wk = (const float*)d_in[3];
    const float* bk = (const float*)d_in[4];
    const float* Wv = (const float*)d_in[5];
    const float* bv = (const float*)d_in[6];
    float* out = (float*)d_out;

    float *q, *k, *v, *lg;
    cudaGetSymbolAddress((void**)&q,  g_q);
    cudaGetSymbolAddress((void**)&k,  g_k);
    cudaGetSymbolAddress((void**)&v,  g_v);
    cudaGetSymbolAddress((void**)&lg, g_logits);

    const int MN = B_ * N_;  // 32768 rows for the projection GEMMs

    // 1) QKV projections: C = x @ W^T + b   (NT, bias)
    {
        dim3 grid(DOUT_ / 128, MN / 128, 1);
        gemm_kernel<0, 1><<<grid, 256>>>(x, Wq, bq, q, MN, DOUT_, DIN_,
                                         DIN_, DIN_, DOUT_, 0, 0, 0);
        gemm_kernel<0, 1><<<grid, 256>>>(x, Wk, bk, k, MN, DOUT_, DIN_,
                                         DIN_, DIN_, DOUT_, 0, 0, 0);
        gemm_kernel<0, 1><<<grid, 256>>>(x, Wv, bv, v, MN, DOUT_, DIN_,
                                         DIN_, DIN_, DOUT_, 0, 0, 0);
    }

    // 2) logits[b] = q[b] @ k[b]^T   (NT, batched over z)
    {
        dim3 grid(N_ / 128, N_ / 128, B_);
        gemm_kernel<0, 0><<<grid, 256>>>(q, k, nullptr, lg, N_, N_, DOUT_,
                                         DOUT_, DOUT_, N_,
                                         (long long)N_ * DOUT_,
                                         (long long)N_ * DOUT_,
                                         (long long)N_ * N_);
    }

    // 3) softmax over batch axis, in place (logits -> attn)
    softmax_b_kernel<<<(N_ * N_) / 256, 256>>>(lg);

    // 4) out[b] = attn[b] @ v[b]   (NN, batched over z)
    {
        dim3 grid(DOUT_ / 128, N_ / 128, B_);
        gemm_kernel<1, 0><<<grid, 256>>>(lg, v, nullptr, out, N_, DOUT_, N_,
                                         N_, DOUT_, DOUT_,
                                         (long long)N_ * N_,
                                         (long long)N_ * DOUT_,
                                         (long long)N_ * DOUT_);
    }
}

// round 4
// speedup vs baseline: 1.4066x; 1.4066x over previous
#include <cuda_runtime.h>
#include <cuda_bf16.h>
#include <cstdint>

#define B_    32
#define N_    1024
#define DIN_  256
#define DOUT_ 256
#define MN_   (B_ * N_)   // 32768

typedef unsigned short ushort_t;

// ---------------- device scratch (no allocation allowed) -------------------
__device__ ushort_t g_xh[MN_ * DIN_];
__device__ ushort_t g_xl[MN_ * DIN_];
__device__ ushort_t g_wqh[DOUT_ * DIN_], g_wql[DOUT_ * DIN_];
__device__ ushort_t g_wkh[DOUT_ * DIN_], g_wkl[DOUT_ * DIN_];
__device__ ushort_t g_wvh[DOUT_ * DIN_], g_wvl[DOUT_ * DIN_];
__device__ ushort_t g_qh[MN_ * DOUT_], g_ql[MN_ * DOUT_];
__device__ ushort_t g_kh[MN_ * DOUT_], g_kl[MN_ * DOUT_];
__device__ ushort_t g_vh[MN_ * DOUT_], g_vl[MN_ * DOUT_];
__device__ float    g_logits[(long long)B_ * N_ * N_];      // 128 MB
__device__ ushort_t g_ah[(long long)B_ * N_ * N_];          // attn hi
__device__ ushort_t g_al[(long long)B_ * N_ * N_];          // attn lo

// ---------------- helpers --------------------------------------------------
__device__ __forceinline__ void split_bf16(float x, ushort_t& h, ushort_t& l)
{
    __nv_bfloat16 hb = __float2bfloat16(x);
    float hf = __bfloat162float(hb);
    __nv_bfloat16 lb = __float2bfloat16(x - hf);
    h = __bfloat16_as_ushort(hb);
    l = __bfloat16_as_ushort(lb);
}

__device__ __forceinline__ void cpa16(void* dst_smem, const void* src_gmem)
{
    unsigned d = (unsigned)__cvta_generic_to_shared(dst_smem);
    asm volatile("cp.async.ca.shared.global [%0], [%1], 16;\n" :: "r"(d), "l"(src_gmem));
}
__device__ __forceinline__ void cpa_commit() { asm volatile("cp.async.commit_group;\n" ::: "memory"); }
__device__ __forceinline__ void cpa_wait1()  { asm volatile("cp.async.wait_group 1;\n" ::: "memory"); }

__device__ __forceinline__ void mma_bf16(float* d, const uint32_t* a, uint32_t b0, uint32_t b1)
{
    asm volatile(
        "mma.sync.aligned.m16n8k16.row.col.f32.bf16.bf16.f32 "
        "{%0,%1,%2,%3},{%4,%5,%6,%7},{%8,%9},{%0,%1,%2,%3};\n"
        : "+f"(d[0]), "+f"(d[1]), "+f"(d[2]), "+f"(d[3])
        : "r"(a[0]), "r"(a[1]), "r"(a[2]), "r"(a[3]), "r"(b0), "r"(b1));
}

// ---------------------------------------------------------------------------
// bf16x3 tensor-core GEMM.
//   C[m,n] = sum_k A[m,k] * B'[k,n] (+ bias[n])
// A given as hi/lo bf16 planes, row-major [M][K] (ld = K dim stride).
// BLAYOUT 0 (NT): B planes are [n][k] row-major.   BLAYOUT 1 (NN): [k][n].
// Tile BM=BN=128, BK=16. 256 threads, warp tile 64x32 (m16n8k16 frags).
// SMEM rows padded to 24 bf16 (12 words) -> conflict-free fragment LDS.
// ---------------------------------------------------------------------------
#define SROW 24   // ushorts per smem row (16 data + 8 pad)

template <int BLAYOUT, int HASBIAS, int SPLITOUT>
__global__ __launch_bounds__(256, 2)
void gemm_bf16x3(const ushort_t* __restrict__ Ah, const ushort_t* __restrict__ Al,
                 const ushort_t* __restrict__ Bh, const ushort_t* __restrict__ Bl,
                 const float* __restrict__ bias,
                 float* __restrict__ Cf, ushort_t* __restrict__ Ch, ushort_t* __restrict__ Cl,
                 int K, int ldA, int ldB, int ldC,
                 long long sA, long long sB, long long sC)
{
    // [mat][buf][plane][128*SROW]
    __shared__ __align__(16) ushort_t smem[2][2][2][128 * SROW];

    const int bz = blockIdx.z;
    Ah += bz * sA;  Al += bz * sA;
    Bh += bz * sB;  Bl += bz * sB;

    const int tid  = threadIdx.x;
    const int row0 = blockIdx.y * 128;
    const int col0 = blockIdx.x * 128;

    const int lane = tid & 31;
    const int wid  = tid >> 5;
    const int wm   = wid & 1;   // 2 warp rows (64 each)
    const int wn   = wid >> 1;  // 4 warp cols (32 each)
    const int g    = lane >> 2;
    const int c    = lane & 3;

    // loaders ---------------------------------------------------------------
    // NT plane load: 128 rows x 16 bf16; thread t -> row t/2, 16B chunk t%2
    const int ntRow = tid >> 1;
    const int ntCh  = (tid & 1) * 8;
    // NN B (v): 16 rows(k) x 128 cols(n); thread t -> k=t/16, 8-col chunk t%16
    const int nnK   = tid >> 4;
    const int nnN   = (tid & 15) * 8;

    auto load_tile = [&](int buf, int k0) {
        // A (always NT layout)
        cpa16(&smem[0][buf][0][ntRow * SROW + ntCh],
              Ah + (long long)(row0 + ntRow) * ldA + k0 + ntCh);
        cpa16(&smem[0][buf][1][ntRow * SROW + ntCh],
              Al + (long long)(row0 + ntRow) * ldA + k0 + ntCh);
        if (BLAYOUT == 0) {
            cpa16(&smem[1][buf][0][ntRow * SROW + ntCh],
                  Bh + (long long)(col0 + ntRow) * ldB + k0 + ntCh);
            cpa16(&smem[1][buf][1][ntRow * SROW + ntCh],
                  Bl + (long long)(col0 + ntRow) * ldB + k0 + ntCh);
        } else {
            // transpose [k][n] -> smem[n][k]
            uint4 dh = *reinterpret_cast<const uint4*>(
                Bh + (long long)(k0 + nnK) * ldB + col0 + nnN);
            uint4 dl = *reinterpret_cast<const uint4*>(
                Bl + (long long)(k0 + nnK) * ldB + col0 + nnN);
            ushort_t th[8], tl[8];
            *reinterpret_cast<uint4*>(th) = dh;
            *reinterpret_cast<uint4*>(tl) = dl;
#pragma unroll
            for (int i = 0; i < 8; i++) {
                smem[1][buf][0][(nnN + i) * SROW + nnK] = th[i];
                smem[1][buf][1][(nnN + i) * SROW + nnK] = tl[i];
            }
        }
    };

    float acc[4][4][4];
#pragma unroll
    for (int a = 0; a < 4; a++)
#pragma unroll
        for (int b = 0; b < 4; b++)
#pragma unroll
            for (int d = 0; d < 4; d++) acc[a][b][d] = 0.0f;

    const int KT = K / 16;
    int buf = 0;

    load_tile(0, 0);
    cpa_commit();

    for (int t = 0; t < KT; t++) {
        if (t + 1 < KT) load_tile(buf ^ 1, (t + 1) * 16);
        cpa_commit();
        cpa_wait1();
        __syncthreads();

        const uint32_t* Awh = reinterpret_cast<const uint32_t*>(smem[0][buf][0]);
        const uint32_t* Awl = reinterpret_cast<const uint32_t*>(smem[0][buf][1]);
        const uint32_t* Bwh = reinterpret_cast<const uint32_t*>(smem[1][buf][0]);
        const uint32_t* Bwl = reinterpret_cast<const uint32_t*>(smem[1][buf][1]);

        uint32_t ah[4][4], al[4][4];
#pragma unroll
        for (int mi = 0; mi < 4; mi++) {
            const int r  = wm * 64 + mi * 16 + g;     // word row stride = 12
            ah[mi][0] = Awh[r * 12 + c];
            ah[mi][1] = Awh[(r + 8) * 12 + c];
            ah[mi][2] = Awh[r * 12 + c + 4];
            ah[mi][3] = Awh[(r + 8) * 12 + c + 4];
            al[mi][0] = Awl[r * 12 + c];
            al[mi][1] = Awl[(r + 8) * 12 + c];
            al[mi][2] = Awl[r * 12 + c + 4];
            al[mi][3] = Awl[(r + 8) * 12 + c + 4];
        }
#pragma unroll
        for (int ni = 0; ni < 4; ni++) {
            const int nr = wn * 32 + ni * 8 + g;
            uint32_t bh0 = Bwh[nr * 12 + c];
            uint32_t bh1 = Bwh[nr * 12 + c + 4];
            uint32_t bl0 = Bwl[nr * 12 + c];
            uint32_t bl1 = Bwl[nr * 12 + c + 4];
#pragma unroll
            for (int mi = 0; mi < 4; mi++) {
                mma_bf16(acc[mi][ni], ah[mi], bh0, bh1);   // hi*hi
                mma_bf16(acc[mi][ni], al[mi], bh0, bh1);   // lo*hi
                mma_bf16(acc[mi][ni], ah[mi], bl0, bl1);   // hi*lo
            }
        }
        __syncthreads();
        buf ^= 1;
    }

    // epilogue ---------------------------------------------------------------
#pragma unroll
    for (int ni = 0; ni < 4; ni++) {
        const int col = col0 + wn * 32 + ni * 8 + c * 2;
        float b0v = 0.f, b1v = 0.f;
        if (HASBIAS) { b0v = bias[col]; b1v = bias[col + 1]; }
#pragma unroll
        for (int mi = 0; mi < 4; mi++) {
            const int r = row0 + wm * 64 + mi * 16 + g;
            float v0 = acc[mi][ni][0] + b0v;
            float v1 = acc[mi][ni][1] + b1v;
            float v2 = acc[mi][ni][2] + b0v;
            float v3 = acc[mi][ni][3] + b1v;
            if (SPLITOUT) {
                ushort_t h0, l0, h1, l1, h2, l2, h3, l3;
                split_bf16(v0, h0, l0); split_bf16(v1, h1, l1);
                split_bf16(v2, h2, l2); split_bf16(v3, h3, l3);
                long long o0 = (long long)(bz * sC) + (long long)r * ldC + col;
                long long o1 = o0 + (long long)8 * ldC;
                *reinterpret_cast<uint32_t*>(Ch + o0) = (uint32_t)h0 | ((uint32_t)h1 << 16);
                *reinterpret_cast<uint32_t*>(Cl + o0) = (uint32_t)l0 | ((uint32_t)l1 << 16);
                *reinterpret_cast<uint32_t*>(Ch + o1) = (uint32_t)h2 | ((uint32_t)h3 << 16);
                *reinterpret_cast<uint32_t*>(Cl + o1) = (uint32_t)l2 | ((uint32_t)l3 << 16);
            } else {
                float* base = Cf + bz * sC;
                *reinterpret_cast<float2*>(&base[(long long)r * ldC + col])       = make_float2(v0, v1);
                *reinterpret_cast<float2*>(&base[(long long)(r + 8) * ldC + col]) = make_float2(v2, v3);
            }
        }
    }
}

// ---------------- split pre-pass -------------------------------------------
__global__ __launch_bounds__(256)
void split_kernel(const float* __restrict__ in, ushort_t* __restrict__ hi,
                  ushort_t* __restrict__ lo, int n4)
{
    int i = blockIdx.x * blockDim.x + threadIdx.x;
    if (i >= n4) return;
    float4 f = reinterpret_cast<const float4*>(in)[i];
    ushort_t h[4], l[4];
    split_bf16(f.x, h[0], l[0]); split_bf16(f.y, h[1], l[1]);
    split_bf16(f.z, h[2], l[2]); split_bf16(f.w, h[3], l[3]);
    uint2 ho, lu;
    ho.x = (uint32_t)h[0] | ((uint32_t)h[1] << 16);
    ho.y = (uint32_t)h[2] | ((uint32_t)h[3] << 16);
    lu.x = (uint32_t)l[0] | ((uint32_t)l[1] << 16);
    lu.y = (uint32_t)l[2] | ((uint32_t)l[3] << 16);
    reinterpret_cast<uint2*>(hi)[i] = ho;
    reinterpret_cast<uint2*>(lo)[i] = lu;
}

// ---------------- softmax over batch axis ----------------------------------
__device__ __forceinline__ float fexp_poly(float x)
{
    float t = fmaxf(x, -100.0f) * 1.4426950408889634f;
    float r = rintf(t);
    float f = t - r;
    float p = 0.0013333558f;
    p = fmaf(p, f, 0.0096181291f);
    p = fmaf(p, f, 0.0555041087f);
    p = fmaf(p, f, 0.2402265070f);
    p = fmaf(p, f, 0.6931471806f);
    p = fmaf(p, f, 1.0f);
    int e = (int)r;
    float sc = __int_as_float((e + 127) << 23);
    return p * sc;
}

__global__ __launch_bounds__(256)
void softmax_b_kernel(const float* __restrict__ lg,
                      ushort_t* __restrict__ ah, ushort_t* __restrict__ al)
{
    const int idx = blockIdx.x * blockDim.x + threadIdx.x;   // n*N + m
    const int stride = N_ * N_;

    float vals[B_];
    float mx = -1e30f;
#pragma unroll
    for (int b = 0; b < B_; b++) {
        vals[b] = lg[(long long)b * stride + idx];
        mx = fmaxf(mx, vals[b]);
    }
    float s = 0.0f;
#pragma unroll
    for (int b = 0; b < B_; b++) {
        float ev = fexp_poly(vals[b] - mx);
        vals[b] = ev;
        s += ev;
    }
    const float inv = 1.0f / s;
#pragma unroll
    for (int b = 0; b < B_; b++) {
        ushort_t h, l;
        split_bf16(vals[b] * inv, h, l);
        ah[(long long)b * stride + idx] = h;
        al[(long long)b * stride + idx] = l;
    }
}

// ---------------------------------------------------------------------------
extern "C" void kernel_launch(void* const* d_in, const int* in_sizes, int n_in,
                              void* d_out, int out_size)
{
    const float* x  = (const float*)d_in[0];
    const float* Wq = (const float*)d_in[1];
    const float* bq = (const float*)d_in[2];
    const float* Wk = (const float*)d_in[3];
    const float* bk = (const float*)d_in[4];
    const float* Wv = (const float*)d_in[5];
    const float* bv = (const float*)d_in[6];
    float* out = (float*)d_out;

    ushort_t *xh, *xl, *wqh, *wql, *wkh, *wkl, *wvh, *wvl;
    ushort_t *qh, *ql, *kh, *kl, *vh, *vl, *ah, *al;
    float* lg;
    cudaGetSymbolAddress((void**)&xh,  g_xh);  cudaGetSymbolAddress((void**)&xl,  g_xl);
    cudaGetSymbolAddress((void**)&wqh, g_wqh); cudaGetSymbolAddress((void**)&wql, g_wql);
    cudaGetSymbolAddress((void**)&wkh, g_wkh); cudaGetSymbolAddress((void**)&wkl, g_wkl);
    cudaGetSymbolAddress((void**)&wvh, g_wvh); cudaGetSymbolAddress((void**)&wvl, g_wvl);
    cudaGetSymbolAddress((void**)&qh,  g_qh);  cudaGetSymbolAddress((void**)&ql,  g_ql);
    cudaGetSymbolAddress((void**)&kh,  g_kh);  cudaGetSymbolAddress((void**)&kl,  g_kl);
    cudaGetSymbolAddress((void**)&vh,  g_vh);  cudaGetSymbolAddress((void**)&vl,  g_vl);
    cudaGetSymbolAddress((void**)&ah,  g_ah);  cudaGetSymbolAddress((void**)&al,  g_al);
    cudaGetSymbolAddress((void**)&lg,  g_logits);

    // 0) split fp32 inputs into bf16 hi/lo planes
    split_kernel<<<(MN_ * DIN_ / 4 + 255) / 256, 256>>>(x, xh, xl, MN_ * DIN_ / 4);
    const int w4 = DOUT_ * DIN_ / 4;
    split_kernel<<<(w4 + 255) / 256, 256>>>(Wq, wqh, wql, w4);
    split_kernel<<<(w4 + 255) / 256, 256>>>(Wk, wkh, wkl, w4);
    split_kernel<<<(w4 + 255) / 256, 256>>>(Wv, wvh, wvl, w4);

    // 1) projections: q/k/v = x @ W^T + b  (NT, bias, split output)
    {
        dim3 grid(DOUT_ / 128, MN_ / 128, 1);
        gemm_bf16x3<0, 1, 1><<<grid, 256>>>(xh, xl, wqh, wql, bq, nullptr, qh, ql,
                                            DIN_, DIN_, DIN_, DOUT_, 0, 0, 0);
        gemm_bf16x3<0, 1, 1><<<grid, 256>>>(xh, xl, wkh, wkl, bk, nullptr, kh, kl,
                                            DIN_, DIN_, DIN_, DOUT_, 0, 0, 0);
        gemm_bf16x3<0, 1, 1><<<grid, 256>>>(xh, xl, wvh, wvl, bv, nullptr, vh, vl,
                                            DIN_, DIN_, DIN_, DOUT_, 0, 0, 0);
    }

    // 2) logits[b] = q[b] @ k[b]^T  (NT, fp32 out)
    {
        dim3 grid(N_ / 128, N_ / 128, B_);
        gemm_bf16x3<0, 0, 0><<<grid, 256>>>(qh, ql, kh, kl, nullptr, lg, nullptr, nullptr,
                                            DOUT_, DOUT_, DOUT_, N_,
                                            (long long)N_ * DOUT_,
                                            (long long)N_ * DOUT_,
                                            (long long)N_ * N_);
    }

    // 3) softmax over batch axis -> attn hi/lo planes
    softmax_b_kernel<<<(N_ * N_) / 256, 256>>>(lg, ah, al);

    // 4) out[b] = attn[b] @ v[b]  (NN, fp32 out to d_out)
    {
        dim3 grid(DOUT_ / 128, N_ / 128, B_);
        gemm_bf16x3<1, 0, 0><<<grid, 256>>>(ah, al, vh, vl, nullptr, out, nullptr, nullptr,
                                            N_, N_, DOUT_, DOUT_,
                                            (long long)N_ * N_,
                                            (long long)N_ * DOUT_,
                                            (long long)N_ * DOUT_);
    }
}

// round 5
// speedup vs baseline: 1.4071x; 1.0004x over previous
#include <cuda_runtime.h>
#include <cuda_bf16.h>
#include <cstdint>

#define B_    32
#define N_    1024
#define DIN_  256
#define DOUT_ 256
#define MN_   (B_ * N_)   // 32768

typedef unsigned short ushort_t;

// ---------------- device scratch (no allocation allowed) -------------------
__device__ ushort_t g_xh[MN_ * DIN_];
__device__ ushort_t g_xl[MN_ * DIN_];
__device__ ushort_t g_wqh[DOUT_ * DIN_], g_wql[DOUT_ * DIN_];
__device__ ushort_t g_wkh[DOUT_ * DIN_], g_wkl[DOUT_ * DIN_];
__device__ ushort_t g_wvh[DOUT_ * DIN_], g_wvl[DOUT_ * DIN_];
__device__ ushort_t g_qh[MN_ * DOUT_], g_ql[MN_ * DOUT_];
__device__ ushort_t g_kh[MN_ * DOUT_], g_kl[MN_ * DOUT_];
__device__ ushort_t g_vh[MN_ * DOUT_], g_vl[MN_ * DOUT_];
__device__ float    g_logits[(long long)B_ * N_ * N_];      // 128 MB
__device__ ushort_t g_ah[(long long)B_ * N_ * N_];          // attn hi
__device__ ushort_t g_al[(long long)B_ * N_ * N_];          // attn lo

// ---------------- helpers --------------------------------------------------
__device__ __forceinline__ void split_bf16(float x, ushort_t& h, ushort_t& l)
{
    __nv_bfloat16 hb = __float2bfloat16(x);
    float hf = __bfloat162float(hb);
    __nv_bfloat16 lb = __float2bfloat16(x - hf);
    h = __bfloat16_as_ushort(hb);
    l = __bfloat16_as_ushort(lb);
}

__device__ __forceinline__ void cpa16(void* dst_smem, const void* src_gmem)
{
    unsigned d = (unsigned)__cvta_generic_to_shared(dst_smem);
    asm volatile("cp.async.ca.shared.global [%0], [%1], 16;\n" :: "r"(d), "l"(src_gmem));
}
__device__ __forceinline__ void cpa_commit() { asm volatile("cp.async.commit_group;\n" ::: "memory"); }
__device__ __forceinline__ void cpa_wait1()  { asm volatile("cp.async.wait_group 1;\n" ::: "memory"); }

__device__ __forceinline__ void mma_bf16(float* d, const uint32_t* a, uint32_t b0, uint32_t b1)
{
    asm volatile(
        "mma.sync.aligned.m16n8k16.row.col.f32.bf16.bf16.f32 "
        "{%0,%1,%2,%3},{%4,%5,%6,%7},{%8,%9},{%0,%1,%2,%3};\n"
        : "+f"(d[0]), "+f"(d[1]), "+f"(d[2]), "+f"(d[3])
        : "r"(a[0]), "r"(a[1]), "r"(a[2]), "r"(a[3]), "r"(b0), "r"(b1));
}

// ---------------------------------------------------------------------------
// bf16x3 tensor-core GEMM.
//   C[m,n] = sum_k A[m,k] * B'[k,n] (+ bias[n])
// A given as hi/lo bf16 planes, row-major [M][K] (ld = K dim stride).
// BLAYOUT 0 (NT): B planes are [n][k] row-major.   BLAYOUT 1 (NN): [k][n].
// Tile BM=BN=128, BK=16. 256 threads, warp tile 64x32 (m16n8k16 frags).
// SMEM rows padded to 24 bf16 (12 words) -> conflict-free fragment LDS.
// ---------------------------------------------------------------------------
#define SROW 24   // ushorts per smem row (16 data + 8 pad)

template <int BLAYOUT, int HASBIAS, int SPLITOUT>
__global__ __launch_bounds__(256, 2)
void gemm_bf16x3(const ushort_t* __restrict__ Ah, const ushort_t* __restrict__ Al,
                 const ushort_t* __restrict__ Bh, const ushort_t* __restrict__ Bl,
                 const float* __restrict__ bias,
                 float* __restrict__ Cf, ushort_t* __restrict__ Ch, ushort_t* __restrict__ Cl,
                 int K, int ldA, int ldB, int ldC,
                 long long sA, long long sB, long long sC)
{
    // [mat][buf][plane][128*SROW]
    __shared__ __align__(16) ushort_t smem[2][2][2][128 * SROW];

    const int bz = blockIdx.z;
    Ah += bz * sA;  Al += bz * sA;
    Bh += bz * sB;  Bl += bz * sB;

    const int tid  = threadIdx.x;
    const int row0 = blockIdx.y * 128;
    const int col0 = blockIdx.x * 128;

    const int lane = tid & 31;
    const int wid  = tid >> 5;
    const int wm   = wid & 1;   // 2 warp rows (64 each)
    const int wn   = wid >> 1;  // 4 warp cols (32 each)
    const int g    = lane >> 2;
    const int c    = lane & 3;

    // loaders ---------------------------------------------------------------
    // NT plane load: 128 rows x 16 bf16; thread t -> row t/2, 16B chunk t%2
    const int ntRow = tid >> 1;
    const int ntCh  = (tid & 1) * 8;
    // NN B (v): 16 rows(k) x 128 cols(n); thread t -> k=t/16, 8-col chunk t%16
    const int nnK   = tid >> 4;
    const int nnN   = (tid & 15) * 8;

    auto load_tile = [&](int buf, int k0) {
        // A (always NT layout)
        cpa16(&smem[0][buf][0][ntRow * SROW + ntCh],
              Ah + (long long)(row0 + ntRow) * ldA + k0 + ntCh);
        cpa16(&smem[0][buf][1][ntRow * SROW + ntCh],
              Al + (long long)(row0 + ntRow) * ldA + k0 + ntCh);
        if (BLAYOUT == 0) {
            cpa16(&smem[1][buf][0][ntRow * SROW + ntCh],
                  Bh + (long long)(col0 + ntRow) * ldB + k0 + ntCh);
            cpa16(&smem[1][buf][1][ntRow * SROW + ntCh],
                  Bl + (long long)(col0 + ntRow) * ldB + k0 + ntCh);
        } else {
            // transpose [k][n] -> smem[n][k]
            uint4 dh = *reinterpret_cast<const uint4*>(
                Bh + (long long)(k0 + nnK) * ldB + col0 + nnN);
            uint4 dl = *reinterpret_cast<const uint4*>(
                Bl + (long long)(k0 + nnK) * ldB + col0 + nnN);
            ushort_t th[8], tl[8];
            *reinterpret_cast<uint4*>(th) = dh;
            *reinterpret_cast<uint4*>(tl) = dl;
#pragma unroll
            for (int i = 0; i < 8; i++) {
                smem[1][buf][0][(nnN + i) * SROW + nnK] = th[i];
                smem[1][buf][1][(nnN + i) * SROW + nnK] = tl[i];
            }
        }
    };

    float acc[4][4][4];
#pragma unroll
    for (int a = 0; a < 4; a++)
#pragma unroll
        for (int b = 0; b < 4; b++)
#pragma unroll
            for (int d = 0; d < 4; d++) acc[a][b][d] = 0.0f;

    const int KT = K / 16;
    int buf = 0;

    load_tile(0, 0);
    cpa_commit();

    for (int t = 0; t < KT; t++) {
        if (t + 1 < KT) load_tile(buf ^ 1, (t + 1) * 16);
        cpa_commit();
        cpa_wait1();
        __syncthreads();

        const uint32_t* Awh = reinterpret_cast<const uint32_t*>(smem[0][buf][0]);
        const uint32_t* Awl = reinterpret_cast<const uint32_t*>(smem[0][buf][1]);
        const uint32_t* Bwh = reinterpret_cast<const uint32_t*>(smem[1][buf][0]);
        const uint32_t* Bwl = reinterpret_cast<const uint32_t*>(smem[1][buf][1]);

        uint32_t ah[4][4], al[4][4];
#pragma unroll
        for (int mi = 0; mi < 4; mi++) {
            const int r  = wm * 64 + mi * 16 + g;     // word row stride = 12
            ah[mi][0] = Awh[r * 12 + c];
            ah[mi][1] = Awh[(r + 8) * 12 + c];
            ah[mi][2] = Awh[r * 12 + c + 4];
            ah[mi][3] = Awh[(r + 8) * 12 + c + 4];
            al[mi][0] = Awl[r * 12 + c];
            al[mi][1] = Awl[(r + 8) * 12 + c];
            al[mi][2] = Awl[r * 12 + c + 4];
            al[mi][3] = Awl[(r + 8) * 12 + c + 4];
        }
#pragma unroll
        for (int ni = 0; ni < 4; ni++) {
            const int nr = wn * 32 + ni * 8 + g;
            uint32_t bh0 = Bwh[nr * 12 + c];
            uint32_t bh1 = Bwh[nr * 12 + c + 4];
            uint32_t bl0 = Bwl[nr * 12 + c];
            uint32_t bl1 = Bwl[nr * 12 + c + 4];
#pragma unroll
            for (int mi = 0; mi < 4; mi++) {
                mma_bf16(acc[mi][ni], ah[mi], bh0, bh1);   // hi*hi
                mma_bf16(acc[mi][ni], al[mi], bh0, bh1);   // lo*hi
                mma_bf16(acc[mi][ni], ah[mi], bl0, bl1);   // hi*lo
            }
        }
        __syncthreads();
        buf ^= 1;
    }

    // epilogue ---------------------------------------------------------------
#pragma unroll
    for (int ni = 0; ni < 4; ni++) {
        const int col = col0 + wn * 32 + ni * 8 + c * 2;
        float b0v = 0.f, b1v = 0.f;
        if (HASBIAS) { b0v = bias[col]; b1v = bias[col + 1]; }
#pragma unroll
        for (int mi = 0; mi < 4; mi++) {
            const int r = row0 + wm * 64 + mi * 16 + g;
            float v0 = acc[mi][ni][0] + b0v;
            float v1 = acc[mi][ni][1] + b1v;
            float v2 = acc[mi][ni][2] + b0v;
            float v3 = acc[mi][ni][3] + b1v;
            if (SPLITOUT) {
                ushort_t h0, l0, h1, l1, h2, l2, h3, l3;
                split_bf16(v0, h0, l0); split_bf16(v1, h1, l1);
                split_bf16(v2, h2, l2); split_bf16(v3, h3, l3);
                long long o0 = (long long)(bz * sC) + (long long)r * ldC + col;
                long long o1 = o0 + (long long)8 * ldC;
                *reinterpret_cast<uint32_t*>(Ch + o0) = (uint32_t)h0 | ((uint32_t)h1 << 16);
                *reinterpret_cast<uint32_t*>(Cl + o0) = (uint32_t)l0 | ((uint32_t)l1 << 16);
                *reinterpret_cast<uint32_t*>(Ch + o1) = (uint32_t)h2 | ((uint32_t)h3 << 16);
                *reinterpret_cast<uint32_t*>(Cl + o1) = (uint32_t)l2 | ((uint32_t)l3 << 16);
            } else {
                float* base = Cf + bz * sC;
                *reinterpret_cast<float2*>(&base[(long long)r * ldC + col])       = make_float2(v0, v1);
                *reinterpret_cast<float2*>(&base[(long long)(r + 8) * ldC + col]) = make_float2(v2, v3);
            }
        }
    }
}

// ---------------- split pre-pass -------------------------------------------
__global__ __launch_bounds__(256)
void split_kernel(const float* __restrict__ in, ushort_t* __restrict__ hi,
                  ushort_t* __restrict__ lo, int n4)
{
    int i = blockIdx.x * blockDim.x + threadIdx.x;
    if (i >= n4) return;
    float4 f = reinterpret_cast<const float4*>(in)[i];
    ushort_t h[4], l[4];
    split_bf16(f.x, h[0], l[0]); split_bf16(f.y, h[1], l[1]);
    split_bf16(f.z, h[2], l[2]); split_bf16(f.w, h[3], l[3]);
    uint2 ho, lu;
    ho.x = (uint32_t)h[0] | ((uint32_t)h[1] << 16);
    ho.y = (uint32_t)h[2] | ((uint32_t)h[3] << 16);
    lu.x = (uint32_t)l[0] | ((uint32_t)l[1] << 16);
    lu.y = (uint32_t)l[2] | ((uint32_t)l[3] << 16);
    reinterpret_cast<uint2*>(hi)[i] = ho;
    reinterpret_cast<uint2*>(lo)[i] = lu;
}

// ---------------- softmax over batch axis ----------------------------------
__device__ __forceinline__ float fexp_poly(float x)
{
    float t = fmaxf(x, -100.0f) * 1.4426950408889634f;
    float r = rintf(t);
    float f = t - r;
    float p = 0.0013333558f;
    p = fmaf(p, f, 0.0096181291f);
    p = fmaf(p, f, 0.0555041087f);
    p = fmaf(p, f, 0.2402265070f);
    p = fmaf(p, f, 0.6931471806f);
    p = fmaf(p, f, 1.0f);
    int e = (int)r;
    float sc = __int_as_float((e + 127) << 23);
    return p * sc;
}

__global__ __launch_bounds__(256)
void softmax_b_kernel(const float* __restrict__ lg,
                      ushort_t* __restrict__ ah, ushort_t* __restrict__ al)
{
    const int idx = blockIdx.x * blockDim.x + threadIdx.x;   // n*N + m
    const int stride = N_ * N_;

    float vals[B_];
    float mx = -1e30f;
#pragma unroll
    for (int b = 0; b < B_; b++) {
        vals[b] = lg[(long long)b * stride + idx];
        mx = fmaxf(mx, vals[b]);
    }
    float s = 0.0f;
#pragma unroll
    for (int b = 0; b < B_; b++) {
        float ev = fexp_poly(vals[b] - mx);
        vals[b] = ev;
        s += ev;
    }
    const float inv = 1.0f / s;
#pragma unroll
    for (int b = 0; b < B_; b++) {
        ushort_t h, l;
        split_bf16(vals[b] * inv, h, l);
        ah[(long long)b * stride + idx] = h;
        al[(long long)b * stride + idx] = l;
    }
}

// ---------------------------------------------------------------------------
extern "C" void kernel_launch(void* const* d_in, const int* in_sizes, int n_in,
                              void* d_out, int out_size)
{
    const float* x  = (const float*)d_in[0];
    const float* Wq = (const float*)d_in[1];
    const float* bq = (const float*)d_in[2];
    const float* Wk = (const float*)d_in[3];
    const float* bk = (const float*)d_in[4];
    const float* Wv = (const float*)d_in[5];
    const float* bv = (const float*)d_in[6];
    float* out = (float*)d_out;

    ushort_t *xh, *xl, *wqh, *wql, *wkh, *wkl, *wvh, *wvl;
    ushort_t *qh, *ql, *kh, *kl, *vh, *vl, *ah, *al;
    float* lg;
    cudaGetSymbolAddress((void**)&xh,  g_xh);  cudaGetSymbolAddress((void**)&xl,  g_xl);
    cudaGetSymbolAddress((void**)&wqh, g_wqh); cudaGetSymbolAddress((void**)&wql, g_wql);
    cudaGetSymbolAddress((void**)&wkh, g_wkh); cudaGetSymbolAddress((void**)&wkl, g_wkl);
    cudaGetSymbolAddress((void**)&wvh, g_wvh); cudaGetSymbolAddress((void**)&wvl, g_wvl);
    cudaGetSymbolAddress((void**)&qh,  g_qh);  cudaGetSymbolAddress((void**)&ql,  g_ql);
    cudaGetSymbolAddress((void**)&kh,  g_kh);  cudaGetSymbolAddress((void**)&kl,  g_kl);
    cudaGetSymbolAddress((void**)&vh,  g_vh);  cudaGetSymbolAddress((void**)&vl,  g_vl);
    cudaGetSymbolAddress((void**)&ah,  g_ah);  cudaGetSymbolAddress((void**)&al,  g_al);
    cudaGetSymbolAddress((void**)&lg,  g_logits);

    // 0) split fp32 inputs into bf16 hi/lo planes
    split_kernel<<<(MN_ * DIN_ / 4 + 255) / 256, 256>>>(x, xh, xl, MN_ * DIN_ / 4);
    const int w4 = DOUT_ * DIN_ / 4;
    split_kernel<<<(w4 + 255) / 256, 256>>>(Wq, wqh, wql, w4);
    split_kernel<<<(w4 + 255) / 256, 256>>>(Wk, wkh, wkl, w4);
    split_kernel<<<(w4 + 255) / 256, 256>>>(Wv, wvh, wvl, w4);

    // 1) projections: q/k/v = x @ W^T + b  (NT, bias, split output)
    {
        dim3 grid(DOUT_ / 128, MN_ / 128, 1);
        gemm_bf16x3<0, 1, 1><<<grid, 256>>>(xh, xl, wqh, wql, bq, nullptr, qh, ql,
                                            DIN_, DIN_, DIN_, DOUT_, 0, 0, 0);
        gemm_bf16x3<0, 1, 1><<<grid, 256>>>(xh, xl, wkh, wkl, bk, nullptr, kh, kl,
                                            DIN_, DIN_, DIN_, DOUT_, 0, 0, 0);
        gemm_bf16x3<0, 1, 1><<<grid, 256>>>(xh, xl, wvh, wvl, bv, nullptr, vh, vl,
                                            DIN_, DIN_, DIN_, DOUT_, 0, 0, 0);
    }

    // 2) logits[b] = q[b] @ k[b]^T  (NT, fp32 out)
    {
        dim3 grid(N_ / 128, N_ / 128, B_);
        gemm_bf16x3<0, 0, 0><<<grid, 256>>>(qh, ql, kh, kl, nullptr, lg, nullptr, nullptr,
                                            DOUT_, DOUT_, DOUT_, N_,
                                            (long long)N_ * DOUT_,
                                            (long long)N_ * DOUT_,
                                            (long long)N_ * N_);
    }

    // 3) softmax over batch axis -> attn hi/lo planes
    softmax_b_kernel<<<(N_ * N_) / 256, 256>>>(lg, ah, al);

    // 4) out[b] = attn[b] @ v[b]  (NN, fp32 out to d_out)
    {
        dim3 grid(DOUT_ / 128, N_ / 128, B_);
        gemm_bf16x3<1, 0, 0><<<grid, 256>>>(ah, al, vh, vl, nullptr, out, nullptr, nullptr,
                                            N_, N_, DOUT_, DOUT_,
                                            (long long)N_ * N_,
                                            (long long)N_ * DOUT_,
                                            (long long)N_ * DOUT_);
    }
}